// round 2
// baseline (speedup 1.0000x reference)
#include <cuda_runtime.h>
#include <cuda_bf16.h>
#include <math.h>

// Problem constants
#define PB 4
#define PS 1024
#define PT 1024
#define PD 512
#define PH 8
#define PHD (PH * PD)      // 4096
#define PBS (PB * PS)      // 4096
#define LN_EPS 1e-5f

// ---------------------------------------------------------------------------
// Scratch (device globals; no allocation allowed)
// ---------------------------------------------------------------------------
__device__ float g_Q[PB * PH * PS * PD];       // 16.8M floats
__device__ float g_K[PB * PH * PS * PD];
__device__ float g_V[PB * PH * PS * PD];
__device__ float g_SC[PB * PH * PS * PT];      // 33.5M floats
__device__ float g_CAT[PB * PS * PHD];         // 16.8M floats
__device__ float g_ATT[PBS * PD];
__device__ float g_X1[PBS * PD];
__device__ float g_X2[PBS * PD];
__device__ float g_FFH[PBS * 4 * PD];          // 8.4M floats
__device__ float g_WB0[PHD * PD];              // folded wo@wf (self-attn)
__device__ float g_WB1[PHD * PD];              // folded wo@wf (cross-attn)
__device__ float g_BT0[PD];
__device__ float g_BT1[PD];

// ---------------------------------------------------------------------------
// Reductions
// ---------------------------------------------------------------------------
__inline__ __device__ float warpRedSum(float v) {
    #pragma unroll
    for (int o = 16; o > 0; o >>= 1) v += __shfl_xor_sync(0xffffffffu, v, o);
    return v;
}
__inline__ __device__ float warpRedMax(float v) {
    #pragma unroll
    for (int o = 16; o > 0; o >>= 1) v = fmaxf(v, __shfl_xor_sync(0xffffffffu, v, o));
    return v;
}

// ---------------------------------------------------------------------------
// Generic batched GEMM:  C[z] = alpha * A[z] @ B[z](^T) + bias[z]
// Tiles: 128x128x8, 256 threads, 8x8 per-thread microtile.
// Batch pointer math: off = (z / zdiv)*sOut + (z % zdiv)*sIn  (per matrix).
// All M,N divisible by 128, K divisible by 8 (guaranteed by problem shapes).
// ---------------------------------------------------------------------------
template <bool TB, bool RELU>
__global__ __launch_bounds__(256, 2)
void gemm_kernel(const float* __restrict__ A, const float* __restrict__ Bm,
                 const float* __restrict__ bias, float* __restrict__ C,
                 int K, int lda, int ldb, int ldc, int zdiv,
                 long long aOut, long long aIn,
                 long long bOut, long long bIn,
                 long long cOut, long long cIn,
                 long long biasIn, float alpha)
{
    const int z  = blockIdx.z;
    const int zo = z / zdiv, zi = z % zdiv;
    A  += zo * aOut + zi * aIn;
    Bm += zo * bOut + zi * bIn;
    C  += zo * cOut + zi * cIn;
    const float* biasP = bias ? (bias + zi * biasIn) : nullptr;

    __shared__ float As[8][128];
    __shared__ float Bs[8][128];

    const int tid  = threadIdx.x;
    const int bm   = blockIdx.y * 128;
    const int bn   = blockIdx.x * 128;

    const int arow = tid >> 1;          // 0..127
    const int acol = (tid & 1) * 4;     // 0 or 4

    float acc[8][8];
    #pragma unroll
    for (int i = 0; i < 8; i++)
        #pragma unroll
        for (int j = 0; j < 8; j++) acc[i][j] = 0.f;

    const int tm = (tid >> 4) * 8;
    const int tn = (tid & 15) * 8;

    for (int k0 = 0; k0 < K; k0 += 8) {
        // A tile: 128 rows x 8 k, transposed into As[k][m]
        float4 av = *(const float4*)(A + (long long)(bm + arow) * lda + k0 + acol);
        As[acol + 0][arow] = av.x; As[acol + 1][arow] = av.y;
        As[acol + 2][arow] = av.z; As[acol + 3][arow] = av.w;
        if (TB) {
            // B is [N,K]: load like A, transposed into Bs[k][n]
            float4 bv = *(const float4*)(Bm + (long long)(bn + arow) * ldb + k0 + acol);
            Bs[acol + 0][arow] = bv.x; Bs[acol + 1][arow] = bv.y;
            Bs[acol + 2][arow] = bv.z; Bs[acol + 3][arow] = bv.w;
        } else {
            // B is [K,N]: direct 8x128
            int krow = tid >> 5, ncol = (tid & 31) * 4;
            *(float4*)&Bs[krow][ncol] =
                *(const float4*)(Bm + (long long)(k0 + krow) * ldb + bn + ncol);
        }
        __syncthreads();
        #pragma unroll
        for (int kk = 0; kk < 8; kk++) {
            float ar[8], br[8];
            #pragma unroll
            for (int i = 0; i < 8; i++) ar[i] = As[kk][tm + i];
            #pragma unroll
            for (int j = 0; j < 8; j++) br[j] = Bs[kk][tn + j];
            #pragma unroll
            for (int i = 0; i < 8; i++)
                #pragma unroll
                for (int j = 0; j < 8; j++) acc[i][j] += ar[i] * br[j];
        }
        __syncthreads();
    }

    #pragma unroll
    for (int i = 0; i < 8; i++) {
        float* crow = C + (long long)(bm + tm + i) * ldc + bn + tn;
        #pragma unroll
        for (int j = 0; j < 8; j++) {
            float v = acc[i][j] * alpha;
            if (biasP) v += biasP[bn + tn + j];
            if (RELU) v = fmaxf(v, 0.f);
            crow[j] = v;
        }
    }
}

// ---------------------------------------------------------------------------
// Row softmax over T with optional causal masking (row s: valid t <= s)
// ---------------------------------------------------------------------------
__global__ void softmax_kernel(float* __restrict__ sc, int S, int T, int causal)
{
    const int s = blockIdx.x;
    const long long z = blockIdx.y;
    float* row = sc + ((long long)z * S + s) * T;
    const int len = causal ? (s + 1) : T;
    const int tid = threadIdx.x;
    __shared__ float red[8];

    float mx = -1e30f;
    for (int t = tid; t < len; t += 256) mx = fmaxf(mx, row[t]);
    mx = warpRedMax(mx);
    if ((tid & 31) == 0) red[tid >> 5] = mx;
    __syncthreads();
    if (tid == 0) {
        float m = red[0];
        #pragma unroll
        for (int w = 1; w < 8; w++) m = fmaxf(m, red[w]);
        red[0] = m;
    }
    __syncthreads();
    mx = red[0];
    __syncthreads();

    float sum = 0.f;
    for (int t = tid; t < len; t += 256) {
        float e = expf(row[t] - mx);
        row[t] = e;
        sum += e;
    }
    sum = warpRedSum(sum);
    if ((tid & 31) == 0) red[tid >> 5] = sum;
    __syncthreads();
    if (tid == 0) {
        float tsum = 0.f;
        #pragma unroll
        for (int w = 0; w < 8; w++) tsum += red[w];
        red[0] = tsum;
    }
    __syncthreads();
    const float inv = 1.0f / red[0];
    for (int t = tid; t < len; t += 256) row[t] *= inv;
    for (int t = len + tid; t < T; t += 256) row[t] = 0.f;
}

// ---------------------------------------------------------------------------
// out = LayerNorm(a + r) * g + b   (rows of D=512, block=128)
// ---------------------------------------------------------------------------
__global__ void add_ln_kernel(const float* __restrict__ a, const float* __restrict__ r,
                              const float* __restrict__ g, const float* __restrict__ b,
                              float* __restrict__ out)
{
    const long long base = (long long)blockIdx.x * PD;
    const int tid = threadIdx.x;
    __shared__ float red[4];

    float v[4];
    float s = 0.f;
    #pragma unroll
    for (int i = 0; i < 4; i++) {
        int idx = tid + i * 128;
        v[i] = a[base + idx] + r[base + idx];
        s += v[i];
    }
    s = warpRedSum(s);
    if ((tid & 31) == 0) red[tid >> 5] = s;
    __syncthreads();
    const float mean = (red[0] + red[1] + red[2] + red[3]) * (1.f / PD);
    __syncthreads();

    float sq = 0.f;
    #pragma unroll
    for (int i = 0; i < 4; i++) { float d = v[i] - mean; sq += d * d; }
    sq = warpRedSum(sq);
    if ((tid & 31) == 0) red[tid >> 5] = sq;
    __syncthreads();
    const float var = (red[0] + red[1] + red[2] + red[3]) * (1.f / PD);
    const float inv = rsqrtf(var + LN_EPS);

    #pragma unroll
    for (int i = 0; i < 4; i++) {
        int idx = tid + i * 128;
        out[base + idx] = (v[i] - mean) * inv * g[idx] + b[idx];
    }
}

// ---------------------------------------------------------------------------
// bias_tot[j] = bf[j] + sum_k bo_flat[k] * wf[k, j]   (k over H*D=4096, j over D)
// one block per output column j
// ---------------------------------------------------------------------------
__global__ void bias_fold_kernel(const float* __restrict__ bo, const float* __restrict__ wf,
                                 const float* __restrict__ bf, float* __restrict__ out)
{
    const int j = blockIdx.x;
    const int tid = threadIdx.x;
    __shared__ float red[8];
    float acc = 0.f;
    for (int k = tid; k < PHD; k += 256) acc += bo[k] * wf[(long long)k * PD + j];
    acc = warpRedSum(acc);
    if ((tid & 31) == 0) red[tid >> 5] = acc;
    __syncthreads();
    if (tid == 0) {
        float t = 0.f;
        #pragma unroll
        for (int w = 0; w < 8; w++) t += red[w];
        out[j] = bf[j] + t;
    }
}

// ---------------------------------------------------------------------------
// Host-side GEMM dispatcher
// ---------------------------------------------------------------------------
static void gemm(const float* A, const float* B, const float* bias, float* C,
                 int M, int N, int K, int lda, int ldb, int ldc,
                 int Z, int zdiv,
                 long long aOut, long long aIn,
                 long long bOut, long long bIn,
                 long long cOut, long long cIn,
                 long long biasIn, float alpha, bool tb, bool relu)
{
    dim3 grid(N / 128, M / 128, Z), block(256);
    if (tb)
        gemm_kernel<true, false><<<grid, block>>>(A, B, bias, C, K, lda, ldb, ldc, zdiv,
                                                  aOut, aIn, bOut, bIn, cOut, cIn, biasIn, alpha);
    else if (relu)
        gemm_kernel<false, true><<<grid, block>>>(A, B, bias, C, K, lda, ldb, ldc, zdiv,
                                                  aOut, aIn, bOut, bIn, cOut, cIn, biasIn, alpha);
    else
        gemm_kernel<false, false><<<grid, block>>>(A, B, bias, C, K, lda, ldb, ldc, zdiv,
                                                   aOut, aIn, bOut, bIn, cOut, cIn, biasIn, alpha);
}

extern "C" void kernel_launch(void* const* d_in, const int* in_sizes, int n_in,
                              void* d_out, int out_size)
{
    (void)in_sizes; (void)n_in; (void)out_size;
    const float* x      = (const float*)d_in[0];
    const float* enc    = (const float*)d_in[1];
    const float* sa_wq  = (const float*)d_in[2];
    const float* sa_bq  = (const float*)d_in[3];
    const float* sa_wk  = (const float*)d_in[4];
    const float* sa_bk  = (const float*)d_in[5];
    const float* sa_wv  = (const float*)d_in[6];
    const float* sa_bv  = (const float*)d_in[7];
    const float* sa_wo  = (const float*)d_in[8];
    const float* sa_bo  = (const float*)d_in[9];
    const float* sa_wf  = (const float*)d_in[10];
    const float* sa_bf  = (const float*)d_in[11];
    const float* ca_wq  = (const float*)d_in[12];
    const float* ca_bq  = (const float*)d_in[13];
    const float* ca_wk  = (const float*)d_in[14];
    const float* ca_bk  = (const float*)d_in[15];
    const float* ca_wv  = (const float*)d_in[16];
    const float* ca_bv  = (const float*)d_in[17];
    const float* ca_wo  = (const float*)d_in[18];
    const float* ca_bo  = (const float*)d_in[19];
    const float* ca_wf  = (const float*)d_in[20];
    const float* ca_bf  = (const float*)d_in[21];
    const float* ln1_g  = (const float*)d_in[22];
    const float* ln1_b  = (const float*)d_in[23];
    const float* ln2_g  = (const float*)d_in[24];
    const float* ln2_b  = (const float*)d_in[25];
    const float* ln3_g  = (const float*)d_in[26];
    const float* ln3_b  = (const float*)d_in[27];
    const float* fc1_w  = (const float*)d_in[28];
    const float* fc1_b  = (const float*)d_in[29];
    const float* fc2_w  = (const float*)d_in[30];
    const float* fc2_b  = (const float*)d_in[31];

    float *Q, *K, *V, *SC, *CAT, *ATT, *X1, *X2, *FFH, *WB0, *WB1, *BT0, *BT1;
    cudaGetSymbolAddress((void**)&Q,   g_Q);
    cudaGetSymbolAddress((void**)&K,   g_K);
    cudaGetSymbolAddress((void**)&V,   g_V);
    cudaGetSymbolAddress((void**)&SC,  g_SC);
    cudaGetSymbolAddress((void**)&CAT, g_CAT);
    cudaGetSymbolAddress((void**)&ATT, g_ATT);
    cudaGetSymbolAddress((void**)&X1,  g_X1);
    cudaGetSymbolAddress((void**)&X2,  g_X2);
    cudaGetSymbolAddress((void**)&FFH, g_FFH);
    cudaGetSymbolAddress((void**)&WB0, g_WB0);
    cudaGetSymbolAddress((void**)&WB1, g_WB1);
    cudaGetSymbolAddress((void**)&BT0, g_BT0);
    cudaGetSymbolAddress((void**)&BT1, g_BT1);

    const long long DD  = (long long)PD * PD;        // 262144
    const long long SD  = (long long)PS * PD;        // 524288
    const long long ST  = (long long)PS * PT;        // 1048576
    const float inv_sqrt_d = 0.04419417382415922f;   // 1/sqrt(512)

    // ---- Fold wo @ wf -> Wbig, bo @ wf + bf -> bias_tot  (both attentions) ----
    gemm(sa_wo, sa_wf, nullptr, WB0, PD, PD, PD, PD, PD, PD,
         PH, PH, 0, DD, 0, DD, 0, DD, 0, 1.f, false, false);
    bias_fold_kernel<<<PD, 256>>>(sa_bo, sa_wf, sa_bf, BT0);
    gemm(ca_wo, ca_wf, nullptr, WB1, PD, PD, PD, PD, PD, PD,
         PH, PH, 0, DD, 0, DD, 0, DD, 0, 1.f, false, false);
    bias_fold_kernel<<<PD, 256>>>(ca_bo, ca_wf, ca_bf, BT1);

    // ======================= Self-attention =======================
    // Per-head projections: z = b*H+h; A = x[b], B = w[h], C = Q[b,h]
    gemm(x, sa_wq, sa_bq, Q, PS, PD, PD, PD, PD, PD,
         PB * PH, PH, SD, 0, 0, DD, (long long)PH * SD, SD, PD, 1.f, false, false);
    gemm(x, sa_wk, sa_bk, K, PS, PD, PD, PD, PD, PD,
         PB * PH, PH, SD, 0, 0, DD, (long long)PH * SD, SD, PD, 1.f, false, false);
    gemm(x, sa_wv, sa_bv, V, PS, PD, PD, PD, PD, PD,
         PB * PH, PH, SD, 0, 0, DD, (long long)PH * SD, SD, PD, 1.f, false, false);
    // scores = Q @ K^T / sqrt(D)
    gemm(Q, K, nullptr, SC, PS, PT, PD, PD, PD, PT,
         PB * PH, PB * PH, 0, SD, 0, SD, 0, ST, 0, inv_sqrt_d, true, false);
    softmax_kernel<<<dim3(PS, PB * PH), 256>>>(SC, PS, PT, 1);
    // cat[b, s, h*D+f] = (A @ V)[b,h,s,f]
    gemm(SC, V, nullptr, CAT, PS, PD, PT, PT, PD, PHD,
         PB * PH, PH, (long long)PH * ST, ST, (long long)PH * SD, SD,
         (long long)PS * PHD, PD, 0, 1.f, false, false);
    // attn = cat @ Wbig + bias_tot
    gemm(CAT, WB0, BT0, ATT, PBS, PD, PHD, PHD, PD, PD,
         1, 1, 0, 0, 0, 0, 0, 0, 0, 1.f, false, false);
    add_ln_kernel<<<PBS, 128>>>(ATT, x, ln1_g, ln1_b, X1);

    // ======================= Cross-attention =======================
    gemm(X1, ca_wq, ca_bq, Q, PS, PD, PD, PD, PD, PD,
         PB * PH, PH, SD, 0, 0, DD, (long long)PH * SD, SD, PD, 1.f, false, false);
    gemm(enc, ca_wk, ca_bk, K, PT, PD, PD, PD, PD, PD,
         PB * PH, PH, (long long)PT * PD, 0, 0, DD, (long long)PH * SD, SD, PD, 1.f, false, false);
    gemm(enc, ca_wv, ca_bv, V, PT, PD, PD, PD, PD, PD,
         PB * PH, PH, (long long)PT * PD, 0, 0, DD, (long long)PH * SD, SD, PD, 1.f, false, false);
    gemm(Q, K, nullptr, SC, PS, PT, PD, PD, PD, PT,
         PB * PH, PB * PH, 0, SD, 0, SD, 0, ST, 0, inv_sqrt_d, true, false);
    softmax_kernel<<<dim3(PS, PB * PH), 256>>>(SC, PS, PT, 0);
    gemm(SC, V, nullptr, CAT, PS, PD, PT, PT, PD, PHD,
         PB * PH, PH, (long long)PH * ST, ST, (long long)PH * SD, SD,
         (long long)PS * PHD, PD, 0, 1.f, false, false);
    gemm(CAT, WB1, BT1, ATT, PBS, PD, PHD, PHD, PD, PD,
         1, 1, 0, 0, 0, 0, 0, 0, 0, 1.f, false, false);
    add_ln_kernel<<<PBS, 128>>>(ATT, X1, ln2_g, ln2_b, X2);

    // ======================= FFN =======================
    gemm(X2, fc1_w, fc1_b, FFH, PBS, 4 * PD, PD, PD, 4 * PD, 4 * PD,
         1, 1, 0, 0, 0, 0, 0, 0, 0, 1.f, false, true);
    gemm(FFH, fc2_w, fc2_b, ATT, PBS, PD, 4 * PD, 4 * PD, PD, PD,
         1, 1, 0, 0, 0, 0, 0, 0, 0, 1.f, false, false);
    add_ln_kernel<<<PBS, 128>>>(ATT, X2, ln3_g, ln3_b, (float*)d_out);
}

// round 10
// speedup vs baseline: 3.0270x; 3.0270x over previous
#include <cuda_runtime.h>
#include <cuda_bf16.h>
#include <math.h>
#include <stdint.h>

// Problem constants
#define PB 4
#define PS 1024
#define PT 1024
#define PD 512
#define PH 8
#define PHD (PH * PD)      // 4096
#define PBS (PB * PS)      // 4096
#define LN_EPS 1e-5f

#define DDc ((long long)PD * PD)     // 262144
#define SDc ((long long)PS * PD)     // 524288
#define STc ((long long)PS * PT)     // 1048576

// ---------------------------------------------------------------------------
// Scratch (device globals; no allocation allowed)
// ---------------------------------------------------------------------------
__device__ float g_Q[PB * PH * PS * PD];
__device__ float g_K[PB * PH * PS * PD];
__device__ float g_V[PB * PH * PS * PD];
__device__ float g_SC[PB * PH * PS * PT];
__device__ float g_CAT[PB * PS * PHD];
__device__ float g_ATT[PBS * PD];
__device__ float g_X1[PBS * PD];
__device__ float g_X2[PBS * PD];
__device__ float g_FFH[PBS * 4 * PD];
__device__ float g_WB[PHD * PD];               // folded wo@wf fp32 (reused sa->ca)
__device__ float g_BT0[PD];
__device__ float g_BT1[PD];

// bf16 hi/lo pre-converted (transposed) B operands
__device__ __nv_bfloat16 g_twq_h[PH * PD * PD], g_twq_l[PH * PD * PD];
__device__ __nv_bfloat16 g_twk_h[PH * PD * PD], g_twk_l[PH * PD * PD];
__device__ __nv_bfloat16 g_twv_h[PH * PD * PD], g_twv_l[PH * PD * PD];
__device__ __nv_bfloat16 g_twf_h[PD * PHD],    g_twf_l[PD * PHD];
__device__ __nv_bfloat16 g_WBT0_h[PD * PHD],   g_WBT0_l[PD * PHD];
__device__ __nv_bfloat16 g_WBT1_h[PD * PHD],   g_WBT1_l[PD * PHD];
__device__ __nv_bfloat16 g_tv_h[PB * PH * PT * PD], g_tv_l[PB * PH * PT * PD];
__device__ __nv_bfloat16 g_tf1_h[2048 * PD],   g_tf1_l[2048 * PD];
__device__ __nv_bfloat16 g_tf2_h[PD * 2048],   g_tf2_l[PD * 2048];

// ---------------------------------------------------------------------------
// Helpers (family-common PTX only: ldmatrix + mma.sync; NO tcgen05/TMA)
// ---------------------------------------------------------------------------
__device__ __forceinline__ uint32_t smem_u32(const void* p) {
    uint32_t a;
    asm("{ .reg .u64 t; cvta.to.shared.u64 t, %1; cvt.u32.u64 %0, t; }"
        : "=r"(a) : "l"(p));
    return a;
}
__device__ __forceinline__ void ldsm4(uint32_t* r, uint32_t addr) {
    asm volatile("ldmatrix.sync.aligned.m8n8.x4.shared.b16 {%0,%1,%2,%3}, [%4];"
                 : "=r"(r[0]), "=r"(r[1]), "=r"(r[2]), "=r"(r[3]) : "r"(addr));
}
__device__ __forceinline__ void mma_bf16(float* c, const uint32_t* a,
                                         uint32_t b0, uint32_t b1) {
    asm volatile(
        "mma.sync.aligned.m16n8k16.row.col.f32.bf16.bf16.f32 "
        "{%0,%1,%2,%3}, {%4,%5,%6,%7}, {%8,%9}, {%0,%1,%2,%3};"
        : "+f"(c[0]), "+f"(c[1]), "+f"(c[2]), "+f"(c[3])
        : "r"(a[0]), "r"(a[1]), "r"(a[2]), "r"(a[3]), "r"(b0), "r"(b1));
}
__device__ __forceinline__ uint32_t bpack(__nv_bfloat16 a, __nv_bfloat16 b) {
    __nv_bfloat162 t = __halves2bfloat162(a, b);
    return *reinterpret_cast<uint32_t*>(&t);
}
__device__ __forceinline__ void cvt_store(char* hi_p, char* lo_p, float4 v) {
    __nv_bfloat16 hx = __float2bfloat16(v.x), hy = __float2bfloat16(v.y),
                  hz = __float2bfloat16(v.z), hw = __float2bfloat16(v.w);
    uint2 h; h.x = bpack(hx, hy); h.y = bpack(hz, hw);
    __nv_bfloat16 lx = __float2bfloat16(v.x - __bfloat162float(hx));
    __nv_bfloat16 ly = __float2bfloat16(v.y - __bfloat162float(hy));
    __nv_bfloat16 lz = __float2bfloat16(v.z - __bfloat162float(hz));
    __nv_bfloat16 lw = __float2bfloat16(v.w - __bfloat162float(hw));
    uint2 l; l.x = bpack(lx, ly); l.y = bpack(lz, lw);
    *(uint2*)hi_p = h; *(uint2*)lo_p = l;
}

// ---------------------------------------------------------------------------
// HMMA bf16x3 GEMM: C[z] = alpha * A[z] @ B[z]^T + bias
// A: fp32 [M,K] row-major (converted to hi/lo bf16 in-kernel)
// B: pre-converted bf16 hi/lo [N,K] (BPRE) or fp32 [N,K] (in-kernel convert)
// Tile 128x128, K-chunk 64, double-buffered SMEM + register prefetch.
// 8 warps (4x2), warp tile 32x64, mma.sync m16n8k16 bf16, fp32 accum.
// SMEM tile layout: bf16 row pitch 72 elems (144B); per stage:
//   [0)Ah [18432)Al [36864)Bh [55296)Bl ; stage stride 73728; 2 stages.
// ---------------------------------------------------------------------------
#define STAGE_B 73728
#define SMEM_DYN (2 * STAGE_B)

template <bool BPRE, bool RELU>
__global__ __launch_bounds__(256, 1)
void mm16_kernel(const float* __restrict__ A, const float* __restrict__ Bf,
                 const __nv_bfloat16* __restrict__ Bhi, const __nv_bfloat16* __restrict__ Blo,
                 const float* __restrict__ bias, float* __restrict__ C,
                 int K, int lda, int ldb, int ldc, int zdiv,
                 long long aOut, long long aIn, long long bOut, long long bIn,
                 long long cOut, long long cIn, long long biasIn, float alpha)
{
    extern __shared__ char sm[];

    const int tid = threadIdx.x;
    const int wid = tid >> 5;
    const int lane = tid & 31;

    const int z = blockIdx.z;
    const int zo = z / zdiv, zi = z % zdiv;
    A += zo * aOut + zi * aIn;
    if (BPRE) { Bhi += zo * bOut + zi * bIn; Blo += zo * bOut + zi * bIn; }
    else      { Bf  += zo * bOut + zi * bIn; }
    C += zo * cOut + zi * cIn;
    const float* biasP = bias ? (bias + zi * biasIn) : nullptr;

    const uint32_t su = smem_u32(sm);
    const int bm = blockIdx.y * 128;
    const int bn = blockIdx.x * 128;
    const int wm = (wid >> 1) * 32;      // warp row origin (4 warps)
    const int wn = (wid & 1) * 64;       // warp col origin (2 warps)
    const int nc = K >> 6;

    // ldmatrix lane-relative offsets (bytes) within Ah / Bh regions
    const uint32_t aOff = (uint32_t)((wm + (lane & 15)) * 144 + (lane >> 4) * 16);
    const uint32_t bOff = (uint32_t)((wn + (lane & 7) + ((lane >> 4) << 3)) * 144
                                     + ((lane >> 3) & 1) * 16);

    // global loader indices: idx = it*256+tid -> r = it*16 + (tid>>4), c4 = tid&15
    const int gr = tid >> 4;
    const int gc = tid & 15;

    float acc[2][8][4] = {};
    float4 pa[8];
    float4 pb[8];
    uint2  pbh[8], pbl[8];

    auto prefetch = [&](int cc) {
        const int k0 = cc << 6;
        const float* Ap = A + (long long)(bm + gr) * lda + k0 + gc * 4;
        #pragma unroll
        for (int it = 0; it < 8; it++)
            pa[it] = *(const float4*)(Ap + (long long)it * 16 * lda);
        if (BPRE) {
            const __nv_bfloat16* Bh = Bhi + (long long)(bn + gr) * ldb + k0 + gc * 4;
            const __nv_bfloat16* Bl = Blo + (long long)(bn + gr) * ldb + k0 + gc * 4;
            #pragma unroll
            for (int it = 0; it < 8; it++) {
                pbh[it] = *(const uint2*)(Bh + (long long)it * 16 * ldb);
                pbl[it] = *(const uint2*)(Bl + (long long)it * 16 * ldb);
            }
        } else {
            const float* Bp = Bf + (long long)(bn + gr) * ldb + k0 + gc * 4;
            #pragma unroll
            for (int it = 0; it < 8; it++)
                pb[it] = *(const float4*)(Bp + (long long)it * 16 * ldb);
        }
    };
    auto store_stage = [&](int buf) {
        char* st = sm + buf * STAGE_B;
        const uint32_t off0 = (uint32_t)(gr * 144 + gc * 8);
        #pragma unroll
        for (int it = 0; it < 8; it++) {
            uint32_t off = off0 + it * 16 * 144;
            cvt_store(st + off, st + 18432 + off, pa[it]);
            if (BPRE) {
                *(uint2*)(st + 36864 + off) = pbh[it];
                *(uint2*)(st + 55296 + off) = pbl[it];
            } else {
                cvt_store(st + 36864 + off, st + 55296 + off, pb[it]);
            }
        }
    };
    auto compute = [&](int buf) {
        const uint32_t sb = su + buf * STAGE_B;
        const uint32_t aBase = sb + aOff;
        const uint32_t bBase = sb + 36864 + bOff;
        #pragma unroll
        for (int ks = 0; ks < 4; ks++) {
            const uint32_t kb = ks * 32;
            uint32_t ah[2][4], al[2][4];
            ldsm4(ah[0], aBase + kb);
            ldsm4(ah[1], aBase + 2304 + kb);
            ldsm4(al[0], aBase + 18432 + kb);
            ldsm4(al[1], aBase + 18432 + 2304 + kb);
            uint32_t bh0[8], bh1[8], bl0[8], bl1[8];
            #pragma unroll
            for (int p = 0; p < 4; p++) {
                uint32_t t[4];
                ldsm4(t, bBase + p * 2304 + kb);
                bh0[2*p] = t[0]; bh1[2*p] = t[1]; bh0[2*p+1] = t[2]; bh1[2*p+1] = t[3];
                ldsm4(t, bBase + 18432 + p * 2304 + kb);
                bl0[2*p] = t[0]; bl1[2*p] = t[1]; bl0[2*p+1] = t[2]; bl1[2*p+1] = t[3];
            }
            #pragma unroll
            for (int mi = 0; mi < 2; mi++)
                #pragma unroll
                for (int nj = 0; nj < 8; nj++) {
                    mma_bf16(acc[mi][nj], ah[mi], bh0[nj], bh1[nj]);
                    mma_bf16(acc[mi][nj], ah[mi], bl0[nj], bl1[nj]);
                    mma_bf16(acc[mi][nj], al[mi], bh0[nj], bh1[nj]);
                }
        }
    };

    prefetch(0);
    store_stage(0);
    __syncthreads();

    for (int cc = 0; cc < nc; cc++) {
        if (cc + 1 < nc) prefetch(cc + 1);
        compute(cc & 1);
        if (cc + 1 < nc) store_stage((cc + 1) & 1);
        __syncthreads();
    }

    // Epilogue: frag (g = lane>>2, t = lane&3): rows g,g+8; cols 2t,2t+1
    const int g = lane >> 2, t4 = lane & 3;
    #pragma unroll
    for (int mi = 0; mi < 2; mi++) {
        const int row0 = bm + wm + mi * 16 + g;
        #pragma unroll
        for (int nj = 0; nj < 8; nj++) {
            const int col = bn + wn + nj * 8 + t4 * 2;
            float b0 = 0.f, b1 = 0.f;
            if (biasP) { b0 = biasP[col]; b1 = biasP[col + 1]; }
            float2 v0, v1;
            v0.x = acc[mi][nj][0] * alpha + b0;
            v0.y = acc[mi][nj][1] * alpha + b1;
            v1.x = acc[mi][nj][2] * alpha + b0;
            v1.y = acc[mi][nj][3] * alpha + b1;
            if (RELU) {
                v0.x = fmaxf(v0.x, 0.f); v0.y = fmaxf(v0.y, 0.f);
                v1.x = fmaxf(v1.x, 0.f); v1.y = fmaxf(v1.y, 0.f);
            }
            *(float2*)(C + (long long)row0 * ldc + col) = v0;
            *(float2*)(C + (long long)(row0 + 8) * ldc + col) = v1;
        }
    }
}

// ---------------------------------------------------------------------------
// Batched transpose + hi/lo bf16 convert: in fp32 [R,C] -> out bf16 [C,R]
// ---------------------------------------------------------------------------
__global__ void tconv_kernel(const float* __restrict__ in,
                             __nv_bfloat16* __restrict__ hi, __nv_bfloat16* __restrict__ lo,
                             int R, int C, long long zIn, long long zOut)
{
    __shared__ float t[32][33];
    const float* inp = in + (long long)blockIdx.z * zIn;
    __nv_bfloat16* oh = hi + (long long)blockIdx.z * zOut;
    __nv_bfloat16* ol = lo + (long long)blockIdx.z * zOut;
    const int r0 = blockIdx.y * 32, c0 = blockIdx.x * 32;
    const int tx = threadIdx.x, ty = threadIdx.y;
    #pragma unroll
    for (int i = 0; i < 4; i++)
        t[ty + 8 * i][tx] = inp[(long long)(r0 + ty + 8 * i) * C + c0 + tx];
    __syncthreads();
    #pragma unroll
    for (int i = 0; i < 4; i++) {
        int y = ty + 8 * i;
        float v = t[tx][y];
        __nv_bfloat16 h = __float2bfloat16(v);
        long long ofs = (long long)(c0 + y) * R + r0 + tx;
        oh[ofs] = h;
        ol[ofs] = __float2bfloat16(v - __bfloat162float(h));
    }
}

// ---------------------------------------------------------------------------
// Reductions / softmax / layernorm / bias-fold
// ---------------------------------------------------------------------------
__inline__ __device__ float warpRedSum(float v) {
    #pragma unroll
    for (int o = 16; o > 0; o >>= 1) v += __shfl_xor_sync(0xffffffffu, v, o);
    return v;
}
__inline__ __device__ float warpRedMax(float v) {
    #pragma unroll
    for (int o = 16; o > 0; o >>= 1) v = fmaxf(v, __shfl_xor_sync(0xffffffffu, v, o));
    return v;
}

__global__ void softmax_kernel(float* __restrict__ sc, int S, int T, int causal)
{
    const int s = blockIdx.x;
    const long long z = blockIdx.y;
    float* row = sc + ((long long)z * S + s) * T;
    const int len = causal ? (s + 1) : T;
    const int tid = threadIdx.x;
    __shared__ float red[8];

    float mx = -1e30f;
    for (int t = tid; t < len; t += 256) mx = fmaxf(mx, row[t]);
    mx = warpRedMax(mx);
    if ((tid & 31) == 0) red[tid >> 5] = mx;
    __syncthreads();
    if (tid == 0) {
        float m = red[0];
        #pragma unroll
        for (int w = 1; w < 8; w++) m = fmaxf(m, red[w]);
        red[0] = m;
    }
    __syncthreads();
    mx = red[0];
    __syncthreads();

    float sum = 0.f;
    for (int t = tid; t < len; t += 256) {
        float e = expf(row[t] - mx);
        row[t] = e;
        sum += e;
    }
    sum = warpRedSum(sum);
    if ((tid & 31) == 0) red[tid >> 5] = sum;
    __syncthreads();
    if (tid == 0) {
        float ts = 0.f;
        #pragma unroll
        for (int w = 0; w < 8; w++) ts += red[w];
        red[0] = ts;
    }
    __syncthreads();
    const float inv = 1.0f / red[0];
    for (int t = tid; t < len; t += 256) row[t] *= inv;
    for (int t = len + tid; t < T; t += 256) row[t] = 0.f;
}

__global__ void add_ln_kernel(const float* __restrict__ a, const float* __restrict__ r,
                              const float* __restrict__ g, const float* __restrict__ b,
                              float* __restrict__ out)
{
    const long long base = (long long)blockIdx.x * PD;
    const int tid = threadIdx.x;
    __shared__ float red[4];

    float v[4];
    float s = 0.f;
    #pragma unroll
    for (int i = 0; i < 4; i++) {
        int idx = tid + i * 128;
        v[i] = a[base + idx] + r[base + idx];
        s += v[i];
    }
    s = warpRedSum(s);
    if ((tid & 31) == 0) red[tid >> 5] = s;
    __syncthreads();
    const float mean = (red[0] + red[1] + red[2] + red[3]) * (1.f / PD);
    __syncthreads();

    float sq = 0.f;
    #pragma unroll
    for (int i = 0; i < 4; i++) { float d = v[i] - mean; sq += d * d; }
    sq = warpRedSum(sq);
    if ((tid & 31) == 0) red[tid >> 5] = sq;
    __syncthreads();
    const float var = (red[0] + red[1] + red[2] + red[3]) * (1.f / PD);
    const float inv = rsqrtf(var + LN_EPS);

    #pragma unroll
    for (int i = 0; i < 4; i++) {
        int idx = tid + i * 128;
        out[base + idx] = (v[i] - mean) * inv * g[idx] + b[idx];
    }
}

__global__ void bias_fold_kernel(const float* __restrict__ bo, const float* __restrict__ wf,
                                 const float* __restrict__ bf, float* __restrict__ out)
{
    const int j = blockIdx.x;
    const int tid = threadIdx.x;
    __shared__ float red[8];
    float acc = 0.f;
    for (int k = tid; k < PHD; k += 256) acc += bo[k] * wf[(long long)k * PD + j];
    acc = warpRedSum(acc);
    if ((tid & 31) == 0) red[tid >> 5] = acc;
    __syncthreads();
    if (tid == 0) {
        float t = 0.f;
        #pragma unroll
        for (int w = 0; w < 8; w++) t += red[w];
        out[j] = bf[j] + t;
    }
}

// ---------------------------------------------------------------------------
// Host dispatchers
// ---------------------------------------------------------------------------
static void mm16(const float* A, const float* Bf,
                 const __nv_bfloat16* Bhi, const __nv_bfloat16* Blo,
                 const float* bias, float* C,
                 int M, int N, int K, int lda, int ldb, int ldc,
                 int Z, int zdiv,
                 long long aOut, long long aIn, long long bOut, long long bIn,
                 long long cOut, long long cIn, long long biasIn,
                 float alpha, bool relu)
{
    dim3 grid(N / 128, M / 128, Z), block(256);
    if (Bhi) {
        if (relu)
            mm16_kernel<true, true><<<grid, block, SMEM_DYN>>>(A, Bf, Bhi, Blo, bias, C,
                K, lda, ldb, ldc, zdiv, aOut, aIn, bOut, bIn, cOut, cIn, biasIn, alpha);
        else
            mm16_kernel<true, false><<<grid, block, SMEM_DYN>>>(A, Bf, Bhi, Blo, bias, C,
                K, lda, ldb, ldc, zdiv, aOut, aIn, bOut, bIn, cOut, cIn, biasIn, alpha);
    } else {
        mm16_kernel<false, false><<<grid, block, SMEM_DYN>>>(A, Bf, Bhi, Blo, bias, C,
            K, lda, ldb, ldc, zdiv, aOut, aIn, bOut, bIn, cOut, cIn, biasIn, alpha);
    }
}

static void tconv(const float* in, __nv_bfloat16* hi, __nv_bfloat16* lo,
                  int R, int C, int Z, long long zIn, long long zOut)
{
    dim3 grid(C / 32, R / 32, Z), block(32, 8);
    tconv_kernel<<<grid, block>>>(in, hi, lo, R, C, zIn, zOut);
}

extern "C" void kernel_launch(void* const* d_in, const int* in_sizes, int n_in,
                              void* d_out, int out_size)
{
    (void)in_sizes; (void)n_in; (void)out_size;
    const float* x      = (const float*)d_in[0];
    const float* enc    = (const float*)d_in[1];
    const float* sa_wq  = (const float*)d_in[2];
    const float* sa_bq  = (const float*)d_in[3];
    const float* sa_wk  = (const float*)d_in[4];
    const float* sa_bk  = (const float*)d_in[5];
    const float* sa_wv  = (const float*)d_in[6];
    const float* sa_bv  = (const float*)d_in[7];
    const float* sa_wo  = (const float*)d_in[8];
    const float* sa_bo  = (const float*)d_in[9];
    const float* sa_wf  = (const float*)d_in[10];
    const float* sa_bf  = (const float*)d_in[11];
    const float* ca_wq  = (const float*)d_in[12];
    const float* ca_bq  = (const float*)d_in[13];
    const float* ca_wk  = (const float*)d_in[14];
    const float* ca_bk  = (const float*)d_in[15];
    const float* ca_wv  = (const float*)d_in[16];
    const float* ca_bv  = (const float*)d_in[17];
    const float* ca_wo  = (const float*)d_in[18];
    const float* ca_bo  = (const float*)d_in[19];
    const float* ca_wf  = (const float*)d_in[20];
    const float* ca_bf  = (const float*)d_in[21];
    const float* ln1_g  = (const float*)d_in[22];
    const float* ln1_b  = (const float*)d_in[23];
    const float* ln2_g  = (const float*)d_in[24];
    const float* ln2_b  = (const float*)d_in[25];
    const float* ln3_g  = (const float*)d_in[26];
    const float* ln3_b  = (const float*)d_in[27];
    const float* fc1_w  = (const float*)d_in[28];
    const float* fc1_b  = (const float*)d_in[29];
    const float* fc2_w  = (const float*)d_in[30];
    const float* fc2_b  = (const float*)d_in[31];

    cudaFuncSetAttribute(mm16_kernel<true, false>,  cudaFuncAttributeMaxDynamicSharedMemorySize, SMEM_DYN);
    cudaFuncSetAttribute(mm16_kernel<true, true>,   cudaFuncAttributeMaxDynamicSharedMemorySize, SMEM_DYN);
    cudaFuncSetAttribute(mm16_kernel<false, false>, cudaFuncAttributeMaxDynamicSharedMemorySize, SMEM_DYN);

    float *Q, *K, *V, *SC, *CAT, *ATT, *X1, *X2, *FFH, *WB, *BT0, *BT1;
    cudaGetSymbolAddress((void**)&Q,   g_Q);
    cudaGetSymbolAddress((void**)&K,   g_K);
    cudaGetSymbolAddress((void**)&V,   g_V);
    cudaGetSymbolAddress((void**)&SC,  g_SC);
    cudaGetSymbolAddress((void**)&CAT, g_CAT);
    cudaGetSymbolAddress((void**)&ATT, g_ATT);
    cudaGetSymbolAddress((void**)&X1,  g_X1);
    cudaGetSymbolAddress((void**)&X2,  g_X2);
    cudaGetSymbolAddress((void**)&FFH, g_FFH);
    cudaGetSymbolAddress((void**)&WB,  g_WB);
    cudaGetSymbolAddress((void**)&BT0, g_BT0);
    cudaGetSymbolAddress((void**)&BT1, g_BT1);

    __nv_bfloat16 *twq_h, *twq_l, *twk_h, *twk_l, *twv_h, *twv_l, *twf_h, *twf_l;
    __nv_bfloat16 *WBT0_h, *WBT0_l, *WBT1_h, *WBT1_l, *tv_h, *tv_l, *tf1_h, *tf1_l, *tf2_h, *tf2_l;
    cudaGetSymbolAddress((void**)&twq_h, g_twq_h);  cudaGetSymbolAddress((void**)&twq_l, g_twq_l);
    cudaGetSymbolAddress((void**)&twk_h, g_twk_h);  cudaGetSymbolAddress((void**)&twk_l, g_twk_l);
    cudaGetSymbolAddress((void**)&twv_h, g_twv_h);  cudaGetSymbolAddress((void**)&twv_l, g_twv_l);
    cudaGetSymbolAddress((void**)&twf_h, g_twf_h);  cudaGetSymbolAddress((void**)&twf_l, g_twf_l);
    cudaGetSymbolAddress((void**)&WBT0_h, g_WBT0_h); cudaGetSymbolAddress((void**)&WBT0_l, g_WBT0_l);
    cudaGetSymbolAddress((void**)&WBT1_h, g_WBT1_h); cudaGetSymbolAddress((void**)&WBT1_l, g_WBT1_l);
    cudaGetSymbolAddress((void**)&tv_h, g_tv_h);    cudaGetSymbolAddress((void**)&tv_l, g_tv_l);
    cudaGetSymbolAddress((void**)&tf1_h, g_tf1_h);  cudaGetSymbolAddress((void**)&tf1_l, g_tf1_l);
    cudaGetSymbolAddress((void**)&tf2_h, g_tf2_h);  cudaGetSymbolAddress((void**)&tf2_l, g_tf2_l);

    const float inv_sqrt_d = 0.04419417382415922f;   // 1/sqrt(512)

    // ---- Fold wo@wf -> WBT (both attentions), bo@wf+bf -> bias_tot ----
    tconv(sa_wf, twf_h, twf_l, PHD, PD, 1, 0, 0);                     // wfT [512,4096]
    mm16(sa_wo, nullptr, twf_h, twf_l, nullptr, WB,
         PD, PD, PD, PD, PHD, PD, PH, PH,
         0, DDc, 0, 512, 0, DDc, 0, 1.f, false);                      // WB = wo@wf
    bias_fold_kernel<<<PD, 256>>>(sa_bo, sa_wf, sa_bf, BT0);
    tconv(WB, WBT0_h, WBT0_l, PHD, PD, 1, 0, 0);                      // WBT0 [512,4096]
    tconv(ca_wf, twf_h, twf_l, PHD, PD, 1, 0, 0);
    mm16(ca_wo, nullptr, twf_h, twf_l, nullptr, WB,
         PD, PD, PD, PD, PHD, PD, PH, PH,
         0, DDc, 0, 512, 0, DDc, 0, 1.f, false);
    bias_fold_kernel<<<PD, 256>>>(ca_bo, ca_wf, ca_bf, BT1);
    tconv(WB, WBT1_h, WBT1_l, PHD, PD, 1, 0, 0);

    // ======================= Self-attention =======================
    tconv(sa_wq, twq_h, twq_l, PD, PD, PH, DDc, DDc);
    tconv(sa_wk, twk_h, twk_l, PD, PD, PH, DDc, DDc);
    tconv(sa_wv, twv_h, twv_l, PD, PD, PH, DDc, DDc);
    mm16(x, nullptr, twq_h, twq_l, sa_bq, Q, PS, PD, PD, PD, PD, PD,
         PB * PH, PH, SDc, 0, 0, DDc, (long long)PH * SDc, SDc, PD, 1.f, false);
    mm16(x, nullptr, twk_h, twk_l, sa_bk, K, PS, PD, PD, PD, PD, PD,
         PB * PH, PH, SDc, 0, 0, DDc, (long long)PH * SDc, SDc, PD, 1.f, false);
    mm16(x, nullptr, twv_h, twv_l, sa_bv, V, PS, PD, PD, PD, PD, PD,
         PB * PH, PH, SDc, 0, 0, DDc, (long long)PH * SDc, SDc, PD, 1.f, false);
    mm16(Q, K, nullptr, nullptr, nullptr, SC, PS, PT, PD, PD, PD, PT,
         PB * PH, PB * PH, 0, SDc, 0, SDc, 0, STc, 0, inv_sqrt_d, false);
    softmax_kernel<<<dim3(PS, PB * PH), 256>>>(SC, PS, PT, 1);
    tconv(V, tv_h, tv_l, PT, PD, PB * PH, SDc, SDc);
    mm16(SC, nullptr, tv_h, tv_l, nullptr, CAT, PS, PD, PT, PT, PT, PHD,
         PB * PH, PH, (long long)PH * STc, STc, (long long)PH * SDc, SDc,
         (long long)PS * PHD, PD, 0, 1.f, false);
    mm16(CAT, nullptr, WBT0_h, WBT0_l, BT0, ATT, PBS, PD, PHD, PHD, PHD, PD,
         1, 1, 0, 0, 0, 0, 0, 0, 0, 1.f, false);
    add_ln_kernel<<<PBS, 128>>>(ATT, x, ln1_g, ln1_b, X1);

    // ======================= Cross-attention =======================
    tconv(ca_wq, twq_h, twq_l, PD, PD, PH, DDc, DDc);
    tconv(ca_wk, twk_h, twk_l, PD, PD, PH, DDc, DDc);
    tconv(ca_wv, twv_h, twv_l, PD, PD, PH, DDc, DDc);
    mm16(X1, nullptr, twq_h, twq_l, ca_bq, Q, PS, PD, PD, PD, PD, PD,
         PB * PH, PH, SDc, 0, 0, DDc, (long long)PH * SDc, SDc, PD, 1.f, false);
    mm16(enc, nullptr, twk_h, twk_l, ca_bk, K, PT, PD, PD, PD, PD, PD,
         PB * PH, PH, (long long)PT * PD, 0, 0, DDc, (long long)PH * SDc, SDc, PD, 1.f, false);
    mm16(enc, nullptr, twv_h, twv_l, ca_bv, V, PT, PD, PD, PD, PD, PD,
         PB * PH, PH, (long long)PT * PD, 0, 0, DDc, (long long)PH * SDc, SDc, PD, 1.f, false);
    mm16(Q, K, nullptr, nullptr, nullptr, SC, PS, PT, PD, PD, PD, PT,
         PB * PH, PB * PH, 0, SDc, 0, SDc, 0, STc, 0, inv_sqrt_d, false);
    softmax_kernel<<<dim3(PS, PB * PH), 256>>>(SC, PS, PT, 0);
    tconv(V, tv_h, tv_l, PT, PD, PB * PH, SDc, SDc);
    mm16(SC, nullptr, tv_h, tv_l, nullptr, CAT, PS, PD, PT, PT, PT, PHD,
         PB * PH, PH, (long long)PH * STc, STc, (long long)PH * SDc, SDc,
         (long long)PS * PHD, PD, 0, 1.f, false);
    mm16(CAT, nullptr, WBT1_h, WBT1_l, BT1, ATT, PBS, PD, PHD, PHD, PHD, PD,
         1, 1, 0, 0, 0, 0, 0, 0, 0, 1.f, false);
    add_ln_kernel<<<PBS, 128>>>(ATT, X1, ln2_g, ln2_b, X2);

    // ======================= FFN =======================
    tconv(fc1_w, tf1_h, tf1_l, PD, 4 * PD, 1, 0, 0);                  // [2048,512]
    mm16(X2, nullptr, tf1_h, tf1_l, fc1_b, FFH, PBS, 4 * PD, PD, PD, PD, 4 * PD,
         1, 1, 0, 0, 0, 0, 0, 0, 0, 1.f, true);
    tconv(fc2_w, tf2_h, tf2_l, 4 * PD, PD, 1, 0, 0);                  // [512,2048]
    mm16(FFH, nullptr, tf2_h, tf2_l, fc2_b, ATT, PBS, PD, 4 * PD, 4 * PD, 4 * PD, PD,
         1, 1, 0, 0, 0, 0, 0, 0, 0, 1.f, false);
    add_ln_kernel<<<PBS, 128>>>(ATT, X2, ln3_g, ln3_b, (float*)d_out);
}